// round 15
// baseline (speedup 1.0000x reference)
#include <cuda_runtime.h>
#include <cstdint>

// Problem constants
#define BSZ 4
#define TLEN 2048
#define CDIM 1024
#define HN 16
#define HDIM 64

// Scratch (device globals; no allocation allowed)
__device__ float g_q [BSZ*HN*TLEN*HDIM];  // [B,H,T,HD] tf32-rounded, pre-scaled 0.125*log2e
__device__ float g_k [BSZ*HN*TLEN*HDIM];  // [B,H,HD,T] tf32-rounded (d-major)
__device__ float g_v [BSZ*HN*TLEN*HDIM];  // [B,H,T,HD] tf32-rounded
__device__ float g_ao[BSZ*TLEN*CDIM];     // [B,T,C]    tf32-rounded
__device__ float g_xc [8192*1024];        // x        tf32-rounded [M][K]
__device__ float g_wat[3072*1024];        // w_attn^T tf32-rounded [N][K]
__device__ float g_wpt[1024*1024];        // w_proj^T tf32-rounded [N][K]

// ---------------------------------------------------------------------------
// helpers
// ---------------------------------------------------------------------------
__device__ __forceinline__ unsigned f2tf32(float x) {
    unsigned y;
    asm("cvt.rna.tf32.f32 %0, %1;" : "=r"(y) : "f"(x));
    return y;
}
__device__ __forceinline__ float ex2(float x) {
    float y;
    asm("ex2.approx.f32 %0, %1;" : "=f"(y) : "f"(x));
    return y;
}
__device__ __forceinline__ void mma_tf32(float c[4],
                                         unsigned a0, unsigned a1, unsigned a2, unsigned a3,
                                         unsigned b0, unsigned b1) {
    asm volatile(
        "mma.sync.aligned.m16n8k8.row.col.f32.tf32.tf32.f32 "
        "{%0,%1,%2,%3}, {%4,%5,%6,%7}, {%8,%9}, {%0,%1,%2,%3};"
        : "+f"(c[0]), "+f"(c[1]), "+f"(c[2]), "+f"(c[3])
        : "r"(a0), "r"(a1), "r"(a2), "r"(a3), "r"(b0), "r"(b1));
}
__device__ __forceinline__ void ldsm4(unsigned r[4], uint32_t addr) {
    asm volatile("ldmatrix.sync.aligned.m8n8.x4.shared.b16 {%0,%1,%2,%3}, [%4];"
                 : "=r"(r[0]), "=r"(r[1]), "=r"(r[2]), "=r"(r[3]) : "r"(addr));
}
__device__ __forceinline__ void cp16(float* dst, const float* src) {
    unsigned d = (unsigned)__cvta_generic_to_shared(dst);
    asm volatile("cp.async.cg.shared.global [%0], [%1], 16;" :: "r"(d), "l"(src));
}
__device__ __forceinline__ uint32_t smem_u32_of(const void* p) {
    return (uint32_t)__cvta_generic_to_shared(p);
}
#define CP_COMMIT() asm volatile("cp.async.commit_group;")
#define CP_WAIT(n)  asm volatile("cp.async.wait_group %0;" :: "n"(n))

#define QSCALE 0.18033688011112042f   // 0.125 * log2(e)

// ---------------------------------------------------------------------------
// input prep: round x; transpose+round weights to [N][K]
// ---------------------------------------------------------------------------
__global__ void cvt_x(const float* __restrict__ in)
{
    int i = blockIdx.x * blockDim.x + threadIdx.x;
    for (; i < 8192*1024/4; i += gridDim.x * blockDim.x) {
        float4 v = ((const float4*)in)[i];
        v.x = __uint_as_float(f2tf32(v.x));
        v.y = __uint_as_float(f2tf32(v.y));
        v.z = __uint_as_float(f2tf32(v.z));
        v.w = __uint_as_float(f2tf32(v.w));
        ((float4*)g_xc)[i] = v;
    }
}

__global__ void transpose_cvt(const float* __restrict__ in, int K, int N, int sel)
{
    __shared__ float t[32][33];
    const int n0 = blockIdx.x * 32, k0 = blockIdx.y * 32;
    const int tx = threadIdx.x, ty = threadIdx.y;   // 32x8
    #pragma unroll
    for (int i = ty; i < 32; i += 8)
        t[i][tx] = in[(size_t)(k0 + i)*N + n0 + tx];
    __syncthreads();
    float* o = sel ? g_wpt : g_wat;
    #pragma unroll
    for (int i = ty; i < 32; i += 8)
        o[(size_t)(n0 + i)*K + k0 + tx] = __uint_as_float(f2tf32(t[tx][i]));
}

// ---------------------------------------------------------------------------
// tf32 GEMM, cp.async 3-stage, ldmatrix fragment loads.
// C[8192 x N] = A[8192 x 1024] @ Bt[N x 1024]^T.
// Block BMx128x16, 128 threads (4 warps). A smem [BM][20], B smem [128n][20].
// EPI 0: scatter q(xQSCALE tf32)/k(d-major tf32)/v(tf32). EPI 1: +bias.
// ---------------------------------------------------------------------------
#define AST 20
#define BS_STAGEv (128*AST)        // 2560 floats

template<int BM, int N, int EPI>
__global__ __launch_bounds__(128) void gemm_cp(
    const float* __restrict__ bias,
    float* __restrict__ out)
{
    const int AS_STAGEv = BM*AST;
    const int MT = BM/32;

    extern __shared__ float sm[];
    float* As = sm;                      // [3][BM][20]
    float* Bs = sm + 3*AS_STAGEv;        // [3][128][20]
    const uint32_t as_u32 = smem_u32_of(As);
    const uint32_t bs_u32 = smem_u32_of(Bs);

    const float* __restrict__ A  = (EPI == 0) ? g_xc  : g_ao;
    const float* __restrict__ Bt = (EPI == 0) ? g_wat : g_wpt;

    const int K = 1024;
    const int NIT = K / 16;              // 64

    const int tid  = threadIdx.x;
    const int wid  = tid >> 5;
    const int lane = tid & 31;
    const int g    = lane >> 2;
    const int q    = lane & 3;
    const int wm   = (wid >> 1) * (BM/2);
    const int wn   = (wid & 1) * 64;
    const int m0   = blockIdx.y * BM;
    const int n0   = blockIdx.x * 128;

    // ldmatrix per-lane offsets (bytes)
    const int arow = (lane & 7) + ((lane >> 3) & 1) * 8;
    const int acol = (lane >> 4) * 4;
    const uint32_t a_off = ((wm + arow)*AST + acol) * 4;
    const int brow = (lane & 7) + (lane >> 4) * 8;
    const int bcol = ((lane >> 3) & 1) * 4;
    const uint32_t b_off = ((wn + brow)*AST + bcol) * 4;

    auto issue = [&](int kt) {
        const int s = kt % 3;
        // A tile: BM rows x 16 k
        if (BM == 128) {
            const int lar = tid >> 2, lac = (tid & 3) << 2;
            #pragma unroll
            for (int i = 0; i < 4; i++)
                cp16(&As[s*AS_STAGEv + (lar + 32*i)*AST + lac],
                     &A[(size_t)(m0 + lar + 32*i)*K + kt*16 + lac]);
        } else {
            const int lar = tid >> 1, lac = (tid & 1) << 3;
            cp16(&As[s*AS_STAGEv + lar*AST + lac],
                 &A[(size_t)(m0 + lar)*K + kt*16 + lac]);
            cp16(&As[s*AS_STAGEv + lar*AST + lac + 4],
                 &A[(size_t)(m0 + lar)*K + kt*16 + lac + 4]);
        }
        // B tile: 128 n-rows x 16 k, each thread owns one row (64B contiguous)
        const float* Bg = &Bt[(size_t)(n0 + tid)*K + kt*16];
        #pragma unroll
        for (int c = 0; c < 4; c++)
            cp16(&Bs[s*BS_STAGEv + tid*AST + c*4], Bg + c*4);
    };

    float acc[BM/32][8][4];
    #pragma unroll
    for (int mt = 0; mt < MT; mt++)
        #pragma unroll
        for (int nt = 0; nt < 8; nt++)
            #pragma unroll
            for (int c = 0; c < 4; c++) acc[mt][nt][c] = 0.f;

    issue(0); CP_COMMIT();
    issue(1); CP_COMMIT();
    CP_WAIT(1);
    __syncthreads();

    for (int it = 0; it < NIT; it++) {
        if (it + 2 < NIT) issue(it + 2);
        CP_COMMIT();

        const int s = it % 3;
        const uint32_t aS = as_u32 + s*AS_STAGEv*4;
        const uint32_t bS = bs_u32 + s*BS_STAGEv*4;

        #pragma unroll
        for (int ks = 0; ks < 2; ks++) {
            unsigned af[BM/32][4];
            #pragma unroll
            for (int mt = 0; mt < MT; mt++)
                ldsm4(af[mt], aS + a_off + mt*(16*AST*4) + ks*32);
            unsigned bf[8][2];
            #pragma unroll
            for (int p = 0; p < 4; p++) {
                unsigned t4[4];
                ldsm4(t4, bS + b_off + p*(16*AST*4) + ks*32);
                bf[2*p  ][0] = t4[0]; bf[2*p  ][1] = t4[1];
                bf[2*p+1][0] = t4[2]; bf[2*p+1][1] = t4[3];
            }
            #pragma unroll
            for (int mt = 0; mt < MT; mt++)
                #pragma unroll
                for (int nt = 0; nt < 8; nt++)
                    mma_tf32(acc[mt][nt], af[mt][0], af[mt][1], af[mt][2], af[mt][3],
                             bf[nt][0], bf[nt][1]);
        }

        CP_WAIT(1);
        __syncthreads();
    }

    #pragma unroll
    for (int mt = 0; mt < MT; mt++) {
        #pragma unroll
        for (int nt = 0; nt < 8; nt++) {
            const int m = m0 + wm + mt*16 + g;
            const int n = n0 + wn + nt*8 + 2*q;
            if (EPI == 0) {
                const int which = n >> 10;
                const int c = n & 1023;
                const int h = c >> 6;
                const int d = c & 63;
                #pragma unroll
                for (int r = 0; r < 2; r++) {
                    const int mm = m + r*8;
                    const int bb = mm >> 11;
                    const int t  = mm & 2047;
                    const size_t bhb = (size_t)(bb*HN + h);
                    if (which == 0) {
                        float2 v2 = make_float2(
                            __uint_as_float(f2tf32(acc[mt][nt][r*2]   * QSCALE)),
                            __uint_as_float(f2tf32(acc[mt][nt][r*2+1] * QSCALE)));
                        *(float2*)&g_q[(bhb*TLEN + t)*HDIM + d] = v2;
                    } else if (which == 1) {
                        g_k[(bhb*HDIM + d    )*TLEN + t] =
                            __uint_as_float(f2tf32(acc[mt][nt][r*2]));
                        g_k[(bhb*HDIM + d + 1)*TLEN + t] =
                            __uint_as_float(f2tf32(acc[mt][nt][r*2+1]));
                    } else {
                        float2 v2 = make_float2(
                            __uint_as_float(f2tf32(acc[mt][nt][r*2])),
                            __uint_as_float(f2tf32(acc[mt][nt][r*2+1])));
                        *(float2*)&g_v[(bhb*TLEN + t)*HDIM + d] = v2;
                    }
                }
            } else {
                const float2 bb = *(const float2*)&bias[n];
                #pragma unroll
                for (int r = 0; r < 2; r++) {
                    const int mm = m + r*8;
                    float2 v2 = make_float2(acc[mt][nt][r*2]   + bb.x,
                                            acc[mt][nt][r*2+1] + bb.y);
                    *(float2*)&out[(size_t)mm * N + n] = v2;
                }
            }
        }
    }
}

// ---------------------------------------------------------------------------
// Tensor-core flash attention (unchanged from R14): q-tile 128, 256 threads,
// key tile 64, K/V double-buffered cp.async (K d-major), exp2-domain softmax
// with raw ex2.approx, 2 blocks/SM.
// ---------------------------------------------------------------------------
#define KST 72
#define PST 68
#define KV_STAGE (64*KST)                       // 4608 floats
#define ATTN_SMEM_FLOATS (4*KV_STAGE + 128*PST) // 27136 -> 108544 B

__global__ __launch_bounds__(256, 2) void attn_tc()
{
    extern __shared__ float sm[];
    float* Kb = sm;                  // [2][64][72]  Kt[d][key]
    float* Vb = sm + 2*KV_STAGE;     // [2][64][72]  V[key][d]
    float* Ps = sm + 4*KV_STAGE;     // [128][68]    Q stage then P

    const int bh  = blockIdx.y;
    const int qi  = (gridDim.x - 1) - blockIdx.x;  // heavy-first
    const int qm0 = qi * 128;
    const int njt = 2*qi + 2;

    const float* Qp = g_q + ((size_t)bh*TLEN + qm0) * HDIM;
    const float* Kg = g_k + (size_t)bh*HDIM*TLEN;   // [d][t]
    const float* Vg = g_v + (size_t)bh*TLEN*HDIM;   // [t][d]

    const int tid  = threadIdx.x;
    const int wid  = tid >> 5;
    const int lane = tid & 31;
    const int g    = lane >> 2;
    const int q    = lane & 3;
    const int wm   = wid * 16;

    auto issueKV = [&](int jt) {
        const int s  = jt & 1;
        const int k0 = jt * 64;
        const int row = tid >> 2;
        const int c0  = (tid & 3) << 2;
        #pragma unroll
        for (int rep = 0; rep < 4; rep++) {
            const int c4 = c0 + rep*16;
            cp16(&Kb[s*KV_STAGE + row*KST + c4], &Kg[(size_t)row*TLEN + k0 + c4]);
            cp16(&Vb[s*KV_STAGE + row*KST + c4], &Vg[(size_t)(k0 + row)*HDIM + c4]);
        }
    };

    issueKV(0); CP_COMMIT();

    for (int i = tid; i < 2048; i += 256) {
        int row = i >> 4;
        int c4  = (i & 15) << 2;
        float4 qv = *(const float4*)(Qp + (size_t)row*HDIM + c4);
        Ps[row*PST + c4+0] = qv.x; Ps[row*PST + c4+1] = qv.y;
        Ps[row*PST + c4+2] = qv.z; Ps[row*PST + c4+3] = qv.w;
    }
    __syncthreads();

    unsigned qf[8][4];
    #pragma unroll
    for (int kc = 0; kc < 8; kc++) {
        const int rows[2] = { wm + g, wm + g + 8 };
        const int cols[2] = { kc*8 + q, kc*8 + q + 4 };
        #pragma unroll
        for (int s = 0; s < 4; s++)
            qf[kc][s] = __float_as_uint(Ps[rows[s & 1]*PST + cols[s >> 1]]);
    }

    float O[8][4];
    #pragma unroll
    for (int nt = 0; nt < 8; nt++)
        #pragma unroll
        for (int c = 0; c < 4; c++) O[nt][c] = 0.f;
    float mrow[2] = { -1e30f, -1e30f };
    float lrow[2] = { 0.f, 0.f };

    CP_WAIT(0);
    __syncthreads();

    for (int jt = 0; jt < njt; jt++) {
        if (jt + 1 < njt) issueKV(jt + 1);
        CP_COMMIT();

        const int k0  = jt * 64;
        const float* Kc = &Kb[(jt & 1)*KV_STAGE];
        const float* Vc = &Vb[(jt & 1)*KV_STAGE];

        float sacc[8][4];
        #pragma unroll
        for (int nt = 0; nt < 8; nt++)
            #pragma unroll
            for (int c = 0; c < 4; c++) sacc[nt][c] = 0.f;

        #pragma unroll
        for (int kc = 0; kc < 8; kc++) {
            unsigned bf[8][2];
            #pragma unroll
            for (int nt = 0; nt < 8; nt++) {
                bf[nt][0] = __float_as_uint(Kc[(kc*8 + q    )*KST + nt*8 + g]);
                bf[nt][1] = __float_as_uint(Kc[(kc*8 + q + 4)*KST + nt*8 + g]);
            }
            #pragma unroll
            for (int nt = 0; nt < 8; nt++)
                mma_tf32(sacc[nt], qf[kc][0], qf[kc][1], qf[kc][2], qf[kc][3],
                         bf[nt][0], bf[nt][1]);
        }

        if (k0 + 63 > qm0 + wm) {
            #pragma unroll
            for (int nt = 0; nt < 8; nt++)
                #pragma unroll
                for (int c = 0; c < 4; c++) {
                    int row = qm0 + wm + g + ((c >> 1) << 3);
                    int col = k0 + nt*8 + 2*q + (c & 1);
                    if (col > row) sacc[nt][c] = -1e30f;
                }
        }

        #pragma unroll
        for (int r = 0; r < 2; r++) {
            float mx = -1e30f;
            #pragma unroll
            for (int nt = 0; nt < 8; nt++)
                mx = fmaxf(mx, fmaxf(sacc[nt][2*r], sacc[nt][2*r+1]));
            mx = fmaxf(mx, __shfl_xor_sync(0xffffffffu, mx, 1));
            mx = fmaxf(mx, __shfl_xor_sync(0xffffffffu, mx, 2));
            float mnew = fmaxf(mrow[r], mx);
            float sum = 0.f;
            #pragma unroll
            for (int nt = 0; nt < 8; nt++) {
                sacc[nt][2*r]   = ex2(sacc[nt][2*r]   - mnew);
                sacc[nt][2*r+1] = ex2(sacc[nt][2*r+1] - mnew);
                sum += sacc[nt][2*r] + sacc[nt][2*r+1];
            }
            sum += __shfl_xor_sync(0xffffffffu, sum, 1);
            sum += __shfl_xor_sync(0xffffffffu, sum, 2);
            float fac = ex2(mrow[r] - mnew);
            lrow[r] = lrow[r] * fac + sum;
            mrow[r] = mnew;
            #pragma unroll
            for (int nt = 0; nt < 8; nt++) {
                O[nt][2*r]   *= fac;
                O[nt][2*r+1] *= fac;
            }
        }

        #pragma unroll
        for (int nt = 0; nt < 8; nt++) {
            uint2 p0 = make_uint2(f2tf32(sacc[nt][0]), f2tf32(sacc[nt][1]));
            uint2 p1 = make_uint2(f2tf32(sacc[nt][2]), f2tf32(sacc[nt][3]));
            *(uint2*)&Ps[(wm + g    )*PST + nt*8 + 2*q] = *(uint2*)&p0;
            *(uint2*)&Ps[(wm + g + 8)*PST + nt*8 + 2*q] = *(uint2*)&p1;
        }
        __syncwarp();

        #pragma unroll
        for (int kc = 0; kc < 8; kc++) {
            unsigned af0 = __float_as_uint(Ps[(wm + g    )*PST + kc*8 + q]);
            unsigned af1 = __float_as_uint(Ps[(wm + g + 8)*PST + kc*8 + q]);
            unsigned af2 = __float_as_uint(Ps[(wm + g    )*PST + kc*8 + q + 4]);
            unsigned af3 = __float_as_uint(Ps[(wm + g + 8)*PST + kc*8 + q + 4]);
            #pragma unroll
            for (int nt = 0; nt < 8; nt++) {
                unsigned b0 = __float_as_uint(Vc[(kc*8 + q    )*KST + nt*8 + g]);
                unsigned b1 = __float_as_uint(Vc[(kc*8 + q + 4)*KST + nt*8 + g]);
                mma_tf32(O[nt], af0, af1, af2, af3, b0, b1);
            }
        }

        CP_WAIT(0);
        __syncthreads();
    }

    const int b = bh >> 4, h = bh & 15;
    #pragma unroll
    for (int r = 0; r < 2; r++) {
        int t = qm0 + wm + g + 8*r;
        float inv = 1.0f / lrow[r];
        #pragma unroll
        for (int nt = 0; nt < 8; nt++) {
            float2 o2 = make_float2(
                __uint_as_float(f2tf32(O[nt][2*r]   * inv)),
                __uint_as_float(f2tf32(O[nt][2*r+1] * inv)));
            *(float2*)&g_ao[((size_t)b*TLEN + t)*CDIM + h*HDIM + nt*8 + 2*q] = o2;
        }
    }
}

// ---------------------------------------------------------------------------
extern "C" void kernel_launch(void* const* d_in, const int* in_sizes, int n_in,
                              void* d_out, int out_size)
{
    const float* x      = (const float*)d_in[0];
    const float* w_attn = (const float*)d_in[1];
    const float* w_proj = (const float*)d_in[2];
    const float* b_proj = (const float*)d_in[3];
    float* out = (float*)d_out;

    const int gemm_smem128 = 3*(128*AST + 128*AST) * 4;   // 61440 B
    const int gemm_smem64  = 3*( 64*AST + 128*AST) * 4;   // 46080 B
    const int attn_smem = ATTN_SMEM_FLOATS * 4;           // 108544 B
    cudaFuncSetAttribute((const void*)gemm_cp<128,3072,0>, cudaFuncAttributeMaxDynamicSharedMemorySize, gemm_smem128);
    cudaFuncSetAttribute((const void*)gemm_cp<64,1024,1>,  cudaFuncAttributeMaxDynamicSharedMemorySize, gemm_smem64);
    cudaFuncSetAttribute((const void*)attn_tc,             cudaFuncAttributeMaxDynamicSharedMemorySize, attn_smem);

    cvt_x<<<512, 256>>>(x);
    transpose_cvt<<<dim3(3072/32, 1024/32), dim3(32, 8)>>>(w_attn, 1024, 3072, 0);
    transpose_cvt<<<dim3(1024/32, 1024/32), dim3(32, 8)>>>(w_proj, 1024, 1024, 1);

    dim3 g1(3072/128, 8192/128);   // (24, 64)
    gemm_cp<128,3072,0><<<g1, 128, gemm_smem128>>>(nullptr, nullptr);

    dim3 g2(TLEN/128, BSZ*HN);     // (16, 64)
    attn_tc<<<g2, 256, attn_smem>>>();

    dim3 g3(1024/128, 8192/64);    // (8, 128)
    gemm_cp<64,1024,1><<<g3, 128, gemm_smem64>>>(b_proj, out);
}

// round 16
// speedup vs baseline: 1.2178x; 1.2178x over previous
#include <cuda_runtime.h>
#include <cstdint>

// Problem constants
#define BSZ 4
#define TLEN 2048
#define CDIM 1024
#define HN 16
#define HDIM 64

// Scratch (device globals; no allocation allowed)
__device__ float g_q [BSZ*HN*TLEN*HDIM];  // [B,H,T,HD] tf32-rounded, pre-scaled 0.125*log2e
__device__ float g_k [BSZ*HN*TLEN*HDIM];  // [B,H,HD,T] tf32-rounded (d-major)
__device__ float g_v [BSZ*HN*TLEN*HDIM];  // [B,H,T,HD] tf32-rounded
__device__ float g_ao[BSZ*TLEN*CDIM];     // [B,T,C]    tf32-rounded
__device__ float g_xc [8192*1024];        // x       tf32-rounded
__device__ float g_wac[1024*3072];        // w_attn  tf32-rounded
__device__ float g_wpc[1024*1024];        // w_proj  tf32-rounded

// ---------------------------------------------------------------------------
// helpers
// ---------------------------------------------------------------------------
__device__ __forceinline__ unsigned f2tf32(float x) {
    unsigned y;
    asm("cvt.rna.tf32.f32 %0, %1;" : "=r"(y) : "f"(x));
    return y;
}
__device__ __forceinline__ float ex2(float x) {
    float y;
    asm("ex2.approx.f32 %0, %1;" : "=f"(y) : "f"(x));
    return y;
}
__device__ __forceinline__ void mma_tf32(float c[4],
                                         unsigned a0, unsigned a1, unsigned a2, unsigned a3,
                                         unsigned b0, unsigned b1) {
    asm volatile(
        "mma.sync.aligned.m16n8k8.row.col.f32.tf32.tf32.f32 "
        "{%0,%1,%2,%3}, {%4,%5,%6,%7}, {%8,%9}, {%0,%1,%2,%3};"
        : "+f"(c[0]), "+f"(c[1]), "+f"(c[2]), "+f"(c[3])
        : "r"(a0), "r"(a1), "r"(a2), "r"(a3), "r"(b0), "r"(b1));
}
__device__ __forceinline__ void cp16(float* dst, const float* src) {
    unsigned d = (unsigned)__cvta_generic_to_shared(dst);
    asm volatile("cp.async.cg.shared.global [%0], [%1], 16;" :: "r"(d), "l"(src));
}
#define CP_COMMIT() asm volatile("cp.async.commit_group;")
#define CP_WAIT(n)  asm volatile("cp.async.wait_group %0;" :: "n"(n))

#define QSCALE 0.18033688011112042f   // 0.125 * log2(e)

// ---------------------------------------------------------------------------
// fused elementwise tf32 rounding of all three inputs (one launch)
// ---------------------------------------------------------------------------
#define NX4 (8192*1024/4)
#define NA4 (1024*3072/4)
#define NP4 (1024*1024/4)

__global__ void cvt_all(const float* __restrict__ x,
                        const float* __restrict__ wa,
                        const float* __restrict__ wp)
{
    const int total = NX4 + NA4 + NP4;
    for (int i = blockIdx.x * blockDim.x + threadIdx.x; i < total;
         i += gridDim.x * blockDim.x) {
        const float4* src;
        float* dst;
        int j = i;
        if (j < NX4)            { src = (const float4*)x;  dst = g_xc;  }
        else if ((j -= NX4) < NA4) { src = (const float4*)wa; dst = g_wac; }
        else                    { j -= NA4; src = (const float4*)wp; dst = g_wpc; }
        float4 v = src[j];
        v.x = __uint_as_float(f2tf32(v.x));
        v.y = __uint_as_float(f2tf32(v.y));
        v.z = __uint_as_float(f2tf32(v.z));
        v.w = __uint_as_float(f2tf32(v.w));
        ((float4*)dst)[j] = v;
    }
}

// ---------------------------------------------------------------------------
// tf32 GEMM, cp.async 3-stage. Block BMx128x16, 128 threads (4 warps).
// BM=128: warp tile 64x64 (qkv).  BM=64: warp tile 32x64 (proj, wave fill).
// EPI 0: scatter q(xQSCALE tf32)/k(d-major tf32)/v(tf32). EPI 1: +bias.
// ---------------------------------------------------------------------------
#define AS_STRIDE 20
#define BS_STRIDE 136
#define BS_STAGE (16*BS_STRIDE)    // 2176 floats

template<int BM, int N, int EPI>
__global__ __launch_bounds__(128) void gemm_cp(
    const float* __restrict__ bias,
    float* __restrict__ out)
{
    const int AS_STAGEv = BM*AS_STRIDE;
    const int MT = BM/32;

    extern __shared__ float sm[];
    float* As = sm;                    // [3][BM][20]
    float* Bs = sm + 3*AS_STAGEv;      // [3][16][136]

    const float* __restrict__ A  = (EPI == 0) ? g_xc  : g_ao;
    const float* __restrict__ Bm = (EPI == 0) ? g_wac : g_wpc;

    const int K = 1024;
    const int NIT = K / 16;            // 64

    const int tid  = threadIdx.x;
    const int wid  = tid >> 5;
    const int lane = tid & 31;
    const int g    = lane >> 2;
    const int q    = lane & 3;
    const int wm   = (wid >> 1) * (BM/2);
    const int wn   = (wid & 1) * 64;
    const int m0   = blockIdx.y * BM;
    const int n0   = blockIdx.x * 128;

    const int lbr = tid >> 5, lbc = (tid & 31) << 2;  // B: rows lbr+4i

    auto issue = [&](int kt) {
        const int s = kt % 3;
        if (BM == 128) {
            const int lar = tid >> 2, lac = (tid & 3) << 2;
            #pragma unroll
            for (int i = 0; i < 4; i++)
                cp16(&As[s*AS_STAGEv + (lar + 32*i)*AS_STRIDE + lac],
                     &A[(size_t)(m0 + lar + 32*i)*K + kt*16 + lac]);
        } else {
            const int lar = tid >> 1, lac = (tid & 1) << 3;
            cp16(&As[s*AS_STAGEv + lar*AS_STRIDE + lac],
                 &A[(size_t)(m0 + lar)*K + kt*16 + lac]);
            cp16(&As[s*AS_STAGEv + lar*AS_STRIDE + lac + 4],
                 &A[(size_t)(m0 + lar)*K + kt*16 + lac + 4]);
        }
        #pragma unroll
        for (int i = 0; i < 4; i++)
            cp16(&Bs[s*BS_STAGE + (lbr + 4*i)*BS_STRIDE + lbc],
                 &Bm[(size_t)(kt*16 + lbr + 4*i)*N + n0 + lbc]);
    };

    float acc[BM/32][8][4];
    #pragma unroll
    for (int mt = 0; mt < MT; mt++)
        #pragma unroll
        for (int nt = 0; nt < 8; nt++)
            #pragma unroll
            for (int c = 0; c < 4; c++) acc[mt][nt][c] = 0.f;

    issue(0); CP_COMMIT();
    issue(1); CP_COMMIT();
    CP_WAIT(1);
    __syncthreads();

    for (int it = 0; it < NIT; it++) {
        if (it + 2 < NIT) issue(it + 2);
        CP_COMMIT();

        const int s = it % 3;
        const float* Ac = &As[s*AS_STAGEv];
        const float* Bc = &Bs[s*BS_STAGE];

        #pragma unroll
        for (int ks = 0; ks < 2; ks++) {
            const int kq = ks*8 + q;
            unsigned af[BM/32][4];
            #pragma unroll
            for (int mt = 0; mt < MT; mt++) {
                const int mb = wm + mt*16 + g;
                af[mt][0] = __float_as_uint(Ac[(mb    )*AS_STRIDE + kq]);
                af[mt][1] = __float_as_uint(Ac[(mb + 8)*AS_STRIDE + kq]);
                af[mt][2] = __float_as_uint(Ac[(mb    )*AS_STRIDE + kq + 4]);
                af[mt][3] = __float_as_uint(Ac[(mb + 8)*AS_STRIDE + kq + 4]);
            }
            unsigned bf[8][2];
            #pragma unroll
            for (int nt = 0; nt < 8; nt++) {
                const int nb = wn + nt*8 + g;
                bf[nt][0] = __float_as_uint(Bc[(ks*8 + q    )*BS_STRIDE + nb]);
                bf[nt][1] = __float_as_uint(Bc[(ks*8 + q + 4)*BS_STRIDE + nb]);
            }
            #pragma unroll
            for (int mt = 0; mt < MT; mt++)
                #pragma unroll
                for (int nt = 0; nt < 8; nt++)
                    mma_tf32(acc[mt][nt], af[mt][0], af[mt][1], af[mt][2], af[mt][3],
                             bf[nt][0], bf[nt][1]);
        }

        CP_WAIT(1);
        __syncthreads();
    }

    #pragma unroll
    for (int mt = 0; mt < MT; mt++) {
        #pragma unroll
        for (int nt = 0; nt < 8; nt++) {
            const int m = m0 + wm + mt*16 + g;
            const int n = n0 + wn + nt*8 + 2*q;
            if (EPI == 0) {
                const int which = n >> 10;
                const int c = n & 1023;
                const int h = c >> 6;
                const int d = c & 63;
                #pragma unroll
                for (int r = 0; r < 2; r++) {
                    const int mm = m + r*8;
                    const int bb = mm >> 11;
                    const int t  = mm & 2047;
                    const size_t bhb = (size_t)(bb*HN + h);
                    if (which == 0) {
                        float2 v2 = make_float2(
                            __uint_as_float(f2tf32(acc[mt][nt][r*2]   * QSCALE)),
                            __uint_as_float(f2tf32(acc[mt][nt][r*2+1] * QSCALE)));
                        *(float2*)&g_q[(bhb*TLEN + t)*HDIM + d] = v2;
                    } else if (which == 1) {
                        g_k[(bhb*HDIM + d    )*TLEN + t] =
                            __uint_as_float(f2tf32(acc[mt][nt][r*2]));
                        g_k[(bhb*HDIM + d + 1)*TLEN + t] =
                            __uint_as_float(f2tf32(acc[mt][nt][r*2+1]));
                    } else {
                        float2 v2 = make_float2(
                            __uint_as_float(f2tf32(acc[mt][nt][r*2])),
                            __uint_as_float(f2tf32(acc[mt][nt][r*2+1])));
                        *(float2*)&g_v[(bhb*TLEN + t)*HDIM + d] = v2;
                    }
                }
            } else {
                const float2 bb = *(const float2*)&bias[n];
                #pragma unroll
                for (int r = 0; r < 2; r++) {
                    const int mm = m + r*8;
                    float2 v2 = make_float2(acc[mt][nt][r*2]   + bb.x,
                                            acc[mt][nt][r*2+1] + bb.y);
                    *(float2*)&out[(size_t)mm * N + n] = v2;
                }
            }
        }
    }
}

// ---------------------------------------------------------------------------
// Tensor-core flash attention (R14 champion): q-tile 128, 256 threads (8
// warps, 16 q-rows each), key tile 64, K/V double-buffered cp.async (K
// d-major). exp2-domain softmax with raw ex2.approx (q pre-scaled by QSCALE).
// 2 blocks/SM.
// ---------------------------------------------------------------------------
#define KST 72
#define PST 68
#define KV_STAGE (64*KST)                       // 4608 floats
#define ATTN_SMEM_FLOATS (4*KV_STAGE + 128*PST) // 27136 -> 108544 B

__global__ __launch_bounds__(256, 2) void attn_tc()
{
    extern __shared__ float sm[];
    float* Kb = sm;                  // [2][64][72]  Kt[d][key]
    float* Vb = sm + 2*KV_STAGE;     // [2][64][72]  V[key][d]
    float* Ps = sm + 4*KV_STAGE;     // [128][68]    Q stage then P

    const int bh  = blockIdx.y;
    const int qi  = (gridDim.x - 1) - blockIdx.x;  // heavy-first
    const int qm0 = qi * 128;
    const int njt = 2*qi + 2;

    const float* Qp = g_q + ((size_t)bh*TLEN + qm0) * HDIM;
    const float* Kg = g_k + (size_t)bh*HDIM*TLEN;   // [d][t]
    const float* Vg = g_v + (size_t)bh*TLEN*HDIM;   // [t][d]

    const int tid  = threadIdx.x;
    const int wid  = tid >> 5;
    const int lane = tid & 31;
    const int g    = lane >> 2;
    const int q    = lane & 3;
    const int wm   = wid * 16;

    auto issueKV = [&](int jt) {
        const int s  = jt & 1;
        const int k0 = jt * 64;
        const int row = tid >> 2;
        const int c0  = (tid & 3) << 2;
        #pragma unroll
        for (int rep = 0; rep < 4; rep++) {
            const int c4 = c0 + rep*16;
            cp16(&Kb[s*KV_STAGE + row*KST + c4], &Kg[(size_t)row*TLEN + k0 + c4]);
            cp16(&Vb[s*KV_STAGE + row*KST + c4], &Vg[(size_t)(k0 + row)*HDIM + c4]);
        }
    };

    issueKV(0); CP_COMMIT();

    for (int i = tid; i < 2048; i += 256) {
        int row = i >> 4;
        int c4  = (i & 15) << 2;
        float4 qv = *(const float4*)(Qp + (size_t)row*HDIM + c4);
        Ps[row*PST + c4+0] = qv.x; Ps[row*PST + c4+1] = qv.y;
        Ps[row*PST + c4+2] = qv.z; Ps[row*PST + c4+3] = qv.w;
    }
    __syncthreads();

    unsigned qf[8][4];
    #pragma unroll
    for (int kc = 0; kc < 8; kc++) {
        const int rows[2] = { wm + g, wm + g + 8 };
        const int cols[2] = { kc*8 + q, kc*8 + q + 4 };
        #pragma unroll
        for (int s = 0; s < 4; s++)
            qf[kc][s] = __float_as_uint(Ps[rows[s & 1]*PST + cols[s >> 1]]);
    }

    float O[8][4];
    #pragma unroll
    for (int nt = 0; nt < 8; nt++)
        #pragma unroll
        for (int c = 0; c < 4; c++) O[nt][c] = 0.f;
    float mrow[2] = { -1e30f, -1e30f };
    float lrow[2] = { 0.f, 0.f };

    CP_WAIT(0);
    __syncthreads();

    for (int jt = 0; jt < njt; jt++) {
        if (jt + 1 < njt) issueKV(jt + 1);
        CP_COMMIT();

        const int k0  = jt * 64;
        const float* Kc = &Kb[(jt & 1)*KV_STAGE];
        const float* Vc = &Vb[(jt & 1)*KV_STAGE];

        float sacc[8][4];
        #pragma unroll
        for (int nt = 0; nt < 8; nt++)
            #pragma unroll
            for (int c = 0; c < 4; c++) sacc[nt][c] = 0.f;

        #pragma unroll
        for (int kc = 0; kc < 8; kc++) {
            unsigned bf[8][2];
            #pragma unroll
            for (int nt = 0; nt < 8; nt++) {
                bf[nt][0] = __float_as_uint(Kc[(kc*8 + q    )*KST + nt*8 + g]);
                bf[nt][1] = __float_as_uint(Kc[(kc*8 + q + 4)*KST + nt*8 + g]);
            }
            #pragma unroll
            for (int nt = 0; nt < 8; nt++)
                mma_tf32(sacc[nt], qf[kc][0], qf[kc][1], qf[kc][2], qf[kc][3],
                         bf[nt][0], bf[nt][1]);
        }

        if (k0 + 63 > qm0 + wm) {
            #pragma unroll
            for (int nt = 0; nt < 8; nt++)
                #pragma unroll
                for (int c = 0; c < 4; c++) {
                    int row = qm0 + wm + g + ((c >> 1) << 3);
                    int col = k0 + nt*8 + 2*q + (c & 1);
                    if (col > row) sacc[nt][c] = -1e30f;
                }
        }

        #pragma unroll
        for (int r = 0; r < 2; r++) {
            float mx = -1e30f;
            #pragma unroll
            for (int nt = 0; nt < 8; nt++)
                mx = fmaxf(mx, fmaxf(sacc[nt][2*r], sacc[nt][2*r+1]));
            mx = fmaxf(mx, __shfl_xor_sync(0xffffffffu, mx, 1));
            mx = fmaxf(mx, __shfl_xor_sync(0xffffffffu, mx, 2));
            float mnew = fmaxf(mrow[r], mx);
            float sum = 0.f;
            #pragma unroll
            for (int nt = 0; nt < 8; nt++) {
                sacc[nt][2*r]   = ex2(sacc[nt][2*r]   - mnew);
                sacc[nt][2*r+1] = ex2(sacc[nt][2*r+1] - mnew);
                sum += sacc[nt][2*r] + sacc[nt][2*r+1];
            }
            sum += __shfl_xor_sync(0xffffffffu, sum, 1);
            sum += __shfl_xor_sync(0xffffffffu, sum, 2);
            float fac = ex2(mrow[r] - mnew);
            lrow[r] = lrow[r] * fac + sum;
            mrow[r] = mnew;
            #pragma unroll
            for (int nt = 0; nt < 8; nt++) {
                O[nt][2*r]   *= fac;
                O[nt][2*r+1] *= fac;
            }
        }

        #pragma unroll
        for (int nt = 0; nt < 8; nt++) {
            uint2 p0 = make_uint2(f2tf32(sacc[nt][0]), f2tf32(sacc[nt][1]));
            uint2 p1 = make_uint2(f2tf32(sacc[nt][2]), f2tf32(sacc[nt][3]));
            *(uint2*)&Ps[(wm + g    )*PST + nt*8 + 2*q] = *(uint2*)&p0;
            *(uint2*)&Ps[(wm + g + 8)*PST + nt*8 + 2*q] = *(uint2*)&p1;
        }
        __syncwarp();

        #pragma unroll
        for (int kc = 0; kc < 8; kc++) {
            unsigned af0 = __float_as_uint(Ps[(wm + g    )*PST + kc*8 + q]);
            unsigned af1 = __float_as_uint(Ps[(wm + g + 8)*PST + kc*8 + q]);
            unsigned af2 = __float_as_uint(Ps[(wm + g    )*PST + kc*8 + q + 4]);
            unsigned af3 = __float_as_uint(Ps[(wm + g + 8)*PST + kc*8 + q + 4]);
            #pragma unroll
            for (int nt = 0; nt < 8; nt++) {
                unsigned b0 = __float_as_uint(Vc[(kc*8 + q    )*KST + nt*8 + g]);
                unsigned b1 = __float_as_uint(Vc[(kc*8 + q + 4)*KST + nt*8 + g]);
                mma_tf32(O[nt], af0, af1, af2, af3, b0, b1);
            }
        }

        CP_WAIT(0);
        __syncthreads();
    }

    const int b = bh >> 4, h = bh & 15;
    #pragma unroll
    for (int r = 0; r < 2; r++) {
        int t = qm0 + wm + g + 8*r;
        float inv = 1.0f / lrow[r];
        #pragma unroll
        for (int nt = 0; nt < 8; nt++) {
            float2 o2 = make_float2(
                __uint_as_float(f2tf32(O[nt][2*r]   * inv)),
                __uint_as_float(f2tf32(O[nt][2*r+1] * inv)));
            *(float2*)&g_ao[((size_t)b*TLEN + t)*CDIM + h*HDIM + nt*8 + 2*q] = o2;
        }
    }
}

// ---------------------------------------------------------------------------
extern "C" void kernel_launch(void* const* d_in, const int* in_sizes, int n_in,
                              void* d_out, int out_size)
{
    const float* x      = (const float*)d_in[0];
    const float* w_attn = (const float*)d_in[1];
    const float* w_proj = (const float*)d_in[2];
    const float* b_proj = (const float*)d_in[3];
    float* out = (float*)d_out;

    const int gemm_smem128 = 3*(128*AS_STRIDE + 16*BS_STRIDE) * 4;  // 56832 B
    const int gemm_smem64  = 3*( 64*AS_STRIDE + 16*BS_STRIDE) * 4;  // 41472 B
    const int attn_smem = ATTN_SMEM_FLOATS * 4;                     // 108544 B
    cudaFuncSetAttribute((const void*)gemm_cp<128,3072,0>, cudaFuncAttributeMaxDynamicSharedMemorySize, gemm_smem128);
    cudaFuncSetAttribute((const void*)gemm_cp<64,1024,1>,  cudaFuncAttributeMaxDynamicSharedMemorySize, gemm_smem64);
    cudaFuncSetAttribute((const void*)attn_tc,             cudaFuncAttributeMaxDynamicSharedMemorySize, attn_smem);

    cvt_all<<<888, 256>>>(x, w_attn, w_proj);

    dim3 g1(3072/128, 8192/128);   // (24, 64)
    gemm_cp<128,3072,0><<<g1, 128, gemm_smem128>>>(nullptr, nullptr);

    dim3 g2(TLEN/128, BSZ*HN);     // (16, 64)
    attn_tc<<<g2, 256, attn_smem>>>();

    dim3 g3(1024/128, 8192/64);    // (8, 128)
    gemm_cp<64,1024,1><<<g3, 128, gemm_smem64>>>(b_proj, out);
}

// round 17
// speedup vs baseline: 1.5191x; 1.2474x over previous
#include <cuda_runtime.h>
#include <cuda_fp16.h>
#include <cstdint>

// Problem constants
#define BSZ 4
#define TLEN 2048
#define CDIM 1024
#define HN 16
#define HDIM 64

// Scratch (device globals; no allocation allowed)
__device__ __half g_q [BSZ*HN*TLEN*HDIM];  // [B,H,T,HD] fp16, pre-scaled 0.125*log2e
__device__ __half g_k [BSZ*HN*TLEN*HDIM];  // [B,H,T,HD] fp16
__device__ __half g_v [BSZ*HN*TLEN*HDIM];  // [B,H,HD,T] fp16 (d-major)
__device__ float  g_ao[BSZ*TLEN*CDIM];     // [B,T,C] tf32-rounded
__device__ float  g_xc [8192*1024];        // x       tf32-rounded
__device__ float  g_wac[1024*3072];        // w_attn  tf32-rounded
__device__ float  g_wpc[1024*1024];        // w_proj  tf32-rounded

// ---------------------------------------------------------------------------
// helpers
// ---------------------------------------------------------------------------
__device__ __forceinline__ unsigned f2tf32(float x) {
    unsigned y;
    asm("cvt.rna.tf32.f32 %0, %1;" : "=r"(y) : "f"(x));
    return y;
}
__device__ __forceinline__ float ex2(float x) {
    float y;
    asm("ex2.approx.f32 %0, %1;" : "=f"(y) : "f"(x));
    return y;
}
__device__ __forceinline__ unsigned packh2(float a, float b) {
    __half2 h = __floats2half2_rn(a, b);
    return *(unsigned*)&h;
}
__device__ __forceinline__ void mma_tf32(float c[4],
                                         unsigned a0, unsigned a1, unsigned a2, unsigned a3,
                                         unsigned b0, unsigned b1) {
    asm volatile(
        "mma.sync.aligned.m16n8k8.row.col.f32.tf32.tf32.f32 "
        "{%0,%1,%2,%3}, {%4,%5,%6,%7}, {%8,%9}, {%0,%1,%2,%3};"
        : "+f"(c[0]), "+f"(c[1]), "+f"(c[2]), "+f"(c[3])
        : "r"(a0), "r"(a1), "r"(a2), "r"(a3), "r"(b0), "r"(b1));
}
__device__ __forceinline__ void mma_f16(float c[4],
                                        unsigned a0, unsigned a1, unsigned a2, unsigned a3,
                                        unsigned b0, unsigned b1) {
    asm volatile(
        "mma.sync.aligned.m16n8k16.row.col.f32.f16.f16.f32 "
        "{%0,%1,%2,%3}, {%4,%5,%6,%7}, {%8,%9}, {%0,%1,%2,%3};"
        : "+f"(c[0]), "+f"(c[1]), "+f"(c[2]), "+f"(c[3])
        : "r"(a0), "r"(a1), "r"(a2), "r"(a3), "r"(b0), "r"(b1));
}
__device__ __forceinline__ void cp16(float* dst, const float* src) {
    unsigned d = (unsigned)__cvta_generic_to_shared(dst);
    asm volatile("cp.async.cg.shared.global [%0], [%1], 16;" :: "r"(d), "l"(src));
}
__device__ __forceinline__ void cp16h(__half* dst, const __half* src) {
    unsigned d = (unsigned)__cvta_generic_to_shared(dst);
    asm volatile("cp.async.cg.shared.global [%0], [%1], 16;" :: "r"(d), "l"(src));
}
#define CP_COMMIT() asm volatile("cp.async.commit_group;")
#define CP_WAIT(n)  asm volatile("cp.async.wait_group %0;" :: "n"(n))

#define QSCALE 0.18033688011112042f   // 0.125 * log2(e)

// ---------------------------------------------------------------------------
// fused elementwise tf32 rounding of all three inputs (one launch)
// ---------------------------------------------------------------------------
#define NX4 (8192*1024/4)
#define NA4 (1024*3072/4)
#define NP4 (1024*1024/4)

__global__ void cvt_all(const float* __restrict__ x,
                        const float* __restrict__ wa,
                        const float* __restrict__ wp)
{
    const int total = NX4 + NA4 + NP4;
    for (int i = blockIdx.x * blockDim.x + threadIdx.x; i < total;
         i += gridDim.x * blockDim.x) {
        const float4* src;
        float* dst;
        int j = i;
        if (j < NX4)            { src = (const float4*)x;  dst = g_xc;  }
        else if ((j -= NX4) < NA4) { src = (const float4*)wa; dst = g_wac; }
        else                    { j -= NA4; src = (const float4*)wp; dst = g_wpc; }
        float4 v = src[j];
        v.x = __uint_as_float(f2tf32(v.x));
        v.y = __uint_as_float(f2tf32(v.y));
        v.z = __uint_as_float(f2tf32(v.z));
        v.w = __uint_as_float(f2tf32(v.w));
        ((float4*)dst)[j] = v;
    }
}

// ---------------------------------------------------------------------------
// tf32 GEMM, cp.async 3-stage. Block BMx128x16, 128 threads (4 warps).
// BM=128: warp tile 64x64 (qkv).  BM=64: warp tile 32x64 (proj, wave fill).
// EPI 0: q/k fp16 [t][d] half2; v fp16 d-major [d][t]. EPI 1: +bias.
// ---------------------------------------------------------------------------
#define AS_STRIDE 20
#define BS_STRIDE 136
#define BS_STAGE (16*BS_STRIDE)

template<int BM, int N, int EPI>
__global__ __launch_bounds__(128) void gemm_cp(
    const float* __restrict__ bias,
    float* __restrict__ out)
{
    const int AS_STAGEv = BM*AS_STRIDE;
    const int MT = BM/32;

    extern __shared__ float sm[];
    float* As = sm;                    // [3][BM][20]
    float* Bs = sm + 3*AS_STAGEv;      // [3][16][136]

    const float* __restrict__ A  = (EPI == 0) ? g_xc  : g_ao;
    const float* __restrict__ Bm = (EPI == 0) ? g_wac : g_wpc;

    const int K = 1024;
    const int NIT = K / 16;            // 64

    const int tid  = threadIdx.x;
    const int wid  = tid >> 5;
    const int lane = tid & 31;
    const int g    = lane >> 2;
    const int q    = lane & 3;
    const int wm   = (wid >> 1) * (BM/2);
    const int wn   = (wid & 1) * 64;
    const int m0   = blockIdx.y * BM;
    const int n0   = blockIdx.x * 128;

    const int lbr = tid >> 5, lbc = (tid & 31) << 2;

    auto issue = [&](int kt) {
        const int s = kt % 3;
        if (BM == 128) {
            const int lar = tid >> 2, lac = (tid & 3) << 2;
            #pragma unroll
            for (int i = 0; i < 4; i++)
                cp16(&As[s*AS_STAGEv + (lar + 32*i)*AS_STRIDE + lac],
                     &A[(size_t)(m0 + lar + 32*i)*K + kt*16 + lac]);
        } else {
            const int lar = tid >> 1, lac = (tid & 1) << 3;
            cp16(&As[s*AS_STAGEv + lar*AS_STRIDE + lac],
                 &A[(size_t)(m0 + lar)*K + kt*16 + lac]);
            cp16(&As[s*AS_STAGEv + lar*AS_STRIDE + lac + 4],
                 &A[(size_t)(m0 + lar)*K + kt*16 + lac + 4]);
        }
        #pragma unroll
        for (int i = 0; i < 4; i++)
            cp16(&Bs[s*BS_STAGE + (lbr + 4*i)*BS_STRIDE + lbc],
                 &Bm[(size_t)(kt*16 + lbr + 4*i)*N + n0 + lbc]);
    };

    float acc[BM/32][8][4];
    #pragma unroll
    for (int mt = 0; mt < MT; mt++)
        #pragma unroll
        for (int nt = 0; nt < 8; nt++)
            #pragma unroll
            for (int c = 0; c < 4; c++) acc[mt][nt][c] = 0.f;

    issue(0); CP_COMMIT();
    issue(1); CP_COMMIT();
    CP_WAIT(1);
    __syncthreads();

    for (int it = 0; it < NIT; it++) {
        if (it + 2 < NIT) issue(it + 2);
        CP_COMMIT();

        const int s = it % 3;
        const float* Ac = &As[s*AS_STAGEv];
        const float* Bc = &Bs[s*BS_STAGE];

        #pragma unroll
        for (int ks = 0; ks < 2; ks++) {
            const int kq = ks*8 + q;
            unsigned af[BM/32][4];
            #pragma unroll
            for (int mt = 0; mt < MT; mt++) {
                const int mb = wm + mt*16 + g;
                af[mt][0] = __float_as_uint(Ac[(mb    )*AS_STRIDE + kq]);
                af[mt][1] = __float_as_uint(Ac[(mb + 8)*AS_STRIDE + kq]);
                af[mt][2] = __float_as_uint(Ac[(mb    )*AS_STRIDE + kq + 4]);
                af[mt][3] = __float_as_uint(Ac[(mb + 8)*AS_STRIDE + kq + 4]);
            }
            unsigned bf[8][2];
            #pragma unroll
            for (int nt = 0; nt < 8; nt++) {
                const int nb = wn + nt*8 + g;
                bf[nt][0] = __float_as_uint(Bc[(ks*8 + q    )*BS_STRIDE + nb]);
                bf[nt][1] = __float_as_uint(Bc[(ks*8 + q + 4)*BS_STRIDE + nb]);
            }
            #pragma unroll
            for (int mt = 0; mt < MT; mt++)
                #pragma unroll
                for (int nt = 0; nt < 8; nt++)
                    mma_tf32(acc[mt][nt], af[mt][0], af[mt][1], af[mt][2], af[mt][3],
                             bf[nt][0], bf[nt][1]);
        }

        CP_WAIT(1);
        __syncthreads();
    }

    #pragma unroll
    for (int mt = 0; mt < MT; mt++) {
        #pragma unroll
        for (int nt = 0; nt < 8; nt++) {
            const int m = m0 + wm + mt*16 + g;
            const int n = n0 + wn + nt*8 + 2*q;
            if (EPI == 0) {
                const int which = n >> 10;
                const int c = n & 1023;
                const int h = c >> 6;
                const int d = c & 63;
                #pragma unroll
                for (int r = 0; r < 2; r++) {
                    const int mm = m + r*8;
                    const int bb = mm >> 11;
                    const int t  = mm & 2047;
                    const size_t bhb = (size_t)(bb*HN + h);
                    if (which == 0) {
                        __half2 h2 = __floats2half2_rn(acc[mt][nt][r*2]   * QSCALE,
                                                       acc[mt][nt][r*2+1] * QSCALE);
                        *(__half2*)&g_q[(bhb*TLEN + t)*HDIM + d] = h2;
                    } else if (which == 1) {
                        __half2 h2 = __floats2half2_rn(acc[mt][nt][r*2],
                                                       acc[mt][nt][r*2+1]);
                        *(__half2*)&g_k[(bhb*TLEN + t)*HDIM + d] = h2;
                    } else {
                        // V stored d-major [bh][d][t] fp16
                        g_v[(bhb*HDIM + d    )*TLEN + t] = __float2half_rn(acc[mt][nt][r*2]);
                        g_v[(bhb*HDIM + d + 1)*TLEN + t] = __float2half_rn(acc[mt][nt][r*2+1]);
                    }
                }
            } else {
                const float2 bb = *(const float2*)&bias[n];
                #pragma unroll
                for (int r = 0; r < 2; r++) {
                    const int mm = m + r*8;
                    float2 v2 = make_float2(acc[mt][nt][r*2]   + bb.x,
                                            acc[mt][nt][r*2+1] + bb.y);
                    *(float2*)&out[(size_t)mm * N + n] = v2;
                }
            }
        }
    }
}

// ---------------------------------------------------------------------------
// fp16 tensor-core flash attention: q-tile 128, 256 threads (8 warps, 16
// q-rows each), key tile 64, K/V double-buffered cp.async.
// m16n8k16 f16 mma (same 10-bit mantissa as tf32, 2x rate).
// P lives in registers (sacc pairs ARE the PV A-fragments). exp2 softmax.
// Smem: K[2][64][72]h + V[2][64][72]h + Q[128][72]h = 55296 B. 2 blocks/SM.
// ---------------------------------------------------------------------------
#define KH 72
#define ATTN_SMEM_BYTES ((2*64*KH + 2*64*KH + 128*KH) * 2)

__global__ __launch_bounds__(256, 2) void attn_tc()
{
    extern __shared__ float smf[];
    __half* Kb = (__half*)smf;           // [2][64][72]  K[key][d]
    __half* Vb = Kb + 2*64*KH;           // [2][64][72]  V[d][key]
    __half* Qs = Vb + 2*64*KH;           // [128][72]    Q[row][d]

    const int bh  = blockIdx.y;
    const int qi  = (gridDim.x - 1) - blockIdx.x;  // heavy-first
    const int qm0 = qi * 128;
    const int njt = 2*qi + 2;

    const __half* Qp = g_q + ((size_t)bh*TLEN + qm0) * HDIM;  // [t][d]
    const __half* Kg = g_k + (size_t)bh*TLEN*HDIM;            // [t][d]
    const __half* Vg = g_v + (size_t)bh*HDIM*TLEN;            // [d][t]

    const int tid  = threadIdx.x;
    const int wid  = tid >> 5;
    const int lane = tid & 31;
    const int g    = lane >> 2;
    const int q    = lane & 3;
    const int wm   = wid * 16;

    // K tile [64 key][64 d] + V tile [64 d][64 key], fp16: 2 cp16 each/thread
    auto issueKV = [&](int jt) {
        const int s  = jt & 1;
        const int k0 = jt * 64;
        const int row = tid >> 2;            // 0..63
        #pragma unroll
        for (int rep = 0; rep < 2; rep++) {
            const int ch = (tid & 3)*2 + rep;          // 0..7, 8 halfs each
            cp16h(&Kb[s*64*KH + row*KH + ch*8], &Kg[(size_t)(k0 + row)*HDIM + ch*8]);
            cp16h(&Vb[s*64*KH + row*KH + ch*8], &Vg[(size_t)row*TLEN + k0 + ch*8]);
        }
    };

    issueKV(0); CP_COMMIT();

    // stage Q fp16 into Qs (stride 72 halfs)
    for (int i = tid; i < 1024; i += 256) {
        int row = i >> 3;
        int c8  = (i & 7) * 8;
        uint4 v = *(const uint4*)&Qp[(size_t)row*HDIM + c8];
        *(uint4*)&Qs[row*KH + c8] = v;
    }
    __syncthreads();

    // hoist Q A-fragments: 4 k16-chunks x 4 regs
    unsigned qf[4][4];
    #pragma unroll
    for (int kc = 0; kc < 4; kc++) {
        const int base = (wm + g)*KH + kc*16 + 2*q;
        qf[kc][0] = *(const unsigned*)&Qs[base];
        qf[kc][1] = *(const unsigned*)&Qs[base + 8*KH];
        qf[kc][2] = *(const unsigned*)&Qs[base + 8];
        qf[kc][3] = *(const unsigned*)&Qs[base + 8*KH + 8];
    }

    float O[8][4];
    #pragma unroll
    for (int nt = 0; nt < 8; nt++)
        #pragma unroll
        for (int c = 0; c < 4; c++) O[nt][c] = 0.f;
    float mrow[2] = { -1e30f, -1e30f };
    float lrow[2] = { 0.f, 0.f };

    CP_WAIT(0);
    __syncthreads();

    for (int jt = 0; jt < njt; jt++) {
        if (jt + 1 < njt) issueKV(jt + 1);
        CP_COMMIT();

        const int k0 = jt * 64;
        const __half* Kc = &Kb[(jt & 1)*64*KH];
        const __half* Vc = &Vb[(jt & 1)*64*KH];

        // ---- S = Q K^T (fp16 mma, exp2-domain logits) ----
        float sacc[8][4];
        #pragma unroll
        for (int nt = 0; nt < 8; nt++)
            #pragma unroll
            for (int c = 0; c < 4; c++) sacc[nt][c] = 0.f;

        #pragma unroll
        for (int kc = 0; kc < 4; kc++) {
            unsigned bf[8][2];
            #pragma unroll
            for (int nt = 0; nt < 8; nt++) {
                const int base = (nt*8 + g)*KH + kc*16 + 2*q;
                bf[nt][0] = *(const unsigned*)&Kc[base];
                bf[nt][1] = *(const unsigned*)&Kc[base + 8];
            }
            #pragma unroll
            for (int nt = 0; nt < 8; nt++)
                mma_f16(sacc[nt], qf[kc][0], qf[kc][1], qf[kc][2], qf[kc][3],
                        bf[nt][0], bf[nt][1]);
        }

        // causal mask
        if (k0 + 63 > qm0 + wm) {
            #pragma unroll
            for (int nt = 0; nt < 8; nt++)
                #pragma unroll
                for (int c = 0; c < 4; c++) {
                    int row = qm0 + wm + g + ((c >> 1) << 3);
                    int col = k0 + nt*8 + 2*q + (c & 1);
                    if (col > row) sacc[nt][c] = -1e30f;
                }
        }

        // ---- online softmax (exp2 domain, raw ex2.approx) ----
        #pragma unroll
        for (int r = 0; r < 2; r++) {
            float mx = -1e30f;
            #pragma unroll
            for (int nt = 0; nt < 8; nt++)
                mx = fmaxf(mx, fmaxf(sacc[nt][2*r], sacc[nt][2*r+1]));
            mx = fmaxf(mx, __shfl_xor_sync(0xffffffffu, mx, 1));
            mx = fmaxf(mx, __shfl_xor_sync(0xffffffffu, mx, 2));
            float mnew = fmaxf(mrow[r], mx);
            float sum = 0.f;
            #pragma unroll
            for (int nt = 0; nt < 8; nt++) {
                sacc[nt][2*r]   = ex2(sacc[nt][2*r]   - mnew);
                sacc[nt][2*r+1] = ex2(sacc[nt][2*r+1] - mnew);
                sum += sacc[nt][2*r] + sacc[nt][2*r+1];
            }
            sum += __shfl_xor_sync(0xffffffffu, sum, 1);
            sum += __shfl_xor_sync(0xffffffffu, sum, 2);
            float fac = ex2(mrow[r] - mnew);
            lrow[r] = lrow[r] * fac + sum;
            mrow[r] = mnew;
            #pragma unroll
            for (int nt = 0; nt < 8; nt++) {
                O[nt][2*r]   *= fac;
                O[nt][2*r+1] *= fac;
            }
        }

        // ---- O += P V : P A-fragments are sacc pairs, packed in regs ----
        #pragma unroll
        for (int kc2 = 0; kc2 < 4; kc2++) {
            const unsigned pa0 = packh2(sacc[2*kc2  ][0], sacc[2*kc2  ][1]);
            const unsigned pa1 = packh2(sacc[2*kc2  ][2], sacc[2*kc2  ][3]);
            const unsigned pa2 = packh2(sacc[2*kc2+1][0], sacc[2*kc2+1][1]);
            const unsigned pa3 = packh2(sacc[2*kc2+1][2], sacc[2*kc2+1][3]);
            #pragma unroll
            for (int nt = 0; nt < 8; nt++) {
                const int base = (nt*8 + g)*KH + kc2*16 + 2*q;   // Vc[d][key]
                unsigned b0 = *(const unsigned*)&Vc[base];
                unsigned b1 = *(const unsigned*)&Vc[base + 8];
                mma_f16(O[nt], pa0, pa1, pa2, pa3, b0, b1);
            }
        }

        CP_WAIT(0);
        __syncthreads();
    }

    // ---- finalize: /l, tf32-round, write g_ao [B,T,C] ----
    const int b = bh >> 4, h = bh & 15;
    #pragma unroll
    for (int r = 0; r < 2; r++) {
        int t = qm0 + wm + g + 8*r;
        float inv = 1.0f / lrow[r];
        #pragma unroll
        for (int nt = 0; nt < 8; nt++) {
            float2 o2 = make_float2(
                __uint_as_float(f2tf32(O[nt][2*r]   * inv)),
                __uint_as_float(f2tf32(O[nt][2*r+1] * inv)));
            *(float2*)&g_ao[((size_t)b*TLEN + t)*CDIM + h*HDIM + nt*8 + 2*q] = o2;
        }
    }
}

// ---------------------------------------------------------------------------
extern "C" void kernel_launch(void* const* d_in, const int* in_sizes, int n_in,
                              void* d_out, int out_size)
{
    const float* x      = (const float*)d_in[0];
    const float* w_attn = (const float*)d_in[1];
    const float* w_proj = (const float*)d_in[2];
    const float* b_proj = (const float*)d_in[3];
    float* out = (float*)d_out;

    const int gemm_smem128 = 3*(128*AS_STRIDE + 16*BS_STRIDE) * 4;  // 56832 B
    const int gemm_smem64  = 3*( 64*AS_STRIDE + 16*BS_STRIDE) * 4;  // 41472 B
    cudaFuncSetAttribute((const void*)gemm_cp<128,3072,0>, cudaFuncAttributeMaxDynamicSharedMemorySize, gemm_smem128);
    cudaFuncSetAttribute((const void*)gemm_cp<64,1024,1>,  cudaFuncAttributeMaxDynamicSharedMemorySize, gemm_smem64);
    cudaFuncSetAttribute((const void*)attn_tc,             cudaFuncAttributeMaxDynamicSharedMemorySize, ATTN_SMEM_BYTES);

    cvt_all<<<888, 256>>>(x, w_attn, w_proj);

    dim3 g1(3072/128, 8192/128);   // (24, 64)
    gemm_cp<128,3072,0><<<g1, 128, gemm_smem128>>>(nullptr, nullptr);

    dim3 g2(TLEN/128, BSZ*HN);     // (16, 64)
    attn_tc<<<g2, 256, ATTN_SMEM_BYTES>>>();

    dim3 g3(1024/128, 8192/64);    // (8, 128)
    gemm_cp<64,1024,1><<<g3, 128, gemm_smem64>>>(b_proj, out);
}